// round 13
// baseline (speedup 1.0000x reference)
#include <cuda_runtime.h>
#include <cuda_bf16.h>
#include <cstdint>

// ---------------------------------------------------------------------------
// ResidualGatedGCN — chunked two-stream overlap:
//   stream0: node_gemm -> scatter_0..11 (event-gated per chunk)
//   stream1: edge_gemm_0..11 (ep chunks; re-read by scatter while L2-hot)
// ---------------------------------------------------------------------------

#define N_NODES 50000
#define N_EDGES 600000
#define CHUNKS  12
#define CHSZ    50000            // 12 x 50000 = 600000

__device__ float g_qkv[(size_t)N_NODES * 384];      // 76.8 MB (pinned in L2)
__device__ float g_ep [(size_t)N_EDGES * 128];      // 307.2 MB (chunk-hot)

#define KC      32
#define APAD    36
#define BPAD    132
#define A_CHUNK_BYTES (128 * APAD * 4)   // 18432
#define B_BYTES       (128 * BPAD * 4)   // 67584
#define GEMM_SMEM     (B_BYTES + 2 * A_CHUNK_BYTES)   // 104448

__device__ __forceinline__ uint32_t f2tf32(float f) {
    uint32_t u;
    asm("cvt.rna.tf32.f32 %0, %1;" : "=r"(u) : "f"(f));
    return u;
}
__device__ __forceinline__ void mma_tf32(float& d0, float& d1, float& d2, float& d3,
                                         uint32_t a0, uint32_t a1, uint32_t a2, uint32_t a3,
                                         uint32_t b0, uint32_t b1)
{
    asm volatile(
        "mma.sync.aligned.m16n8k8.row.col.f32.tf32.tf32.f32 "
        "{%0,%1,%2,%3}, {%4,%5,%6,%7}, {%8,%9}, {%0,%1,%2,%3};"
        : "+f"(d0), "+f"(d1), "+f"(d2), "+f"(d3)
        : "r"(a0), "r"(a1), "r"(a2), "r"(a3), "r"(b0), "r"(b1));
}
__device__ __forceinline__ uint32_t smem_u32(const void* p) {
    uint32_t a;
    asm("{ .reg .u64 t; cvta.to.shared.u64 t, %1; cvt.u32.u64 %0, t; }"
        : "=r"(a) : "l"(p));
    return a;
}
__device__ __forceinline__ uint64_t policy_evict_first() {
    uint64_t pol;
    asm("createpolicy.fractional.L2::evict_first.b64 %0, 1.0;" : "=l"(pol));
    return pol;
}
__device__ __forceinline__ uint64_t policy_evict_last() {
    uint64_t pol;
    asm("createpolicy.fractional.L2::evict_last.b64 %0, 1.0;" : "=l"(pol));
    return pol;
}
__device__ __forceinline__ void cp_async16_pol(uint32_t sdst, const void* gsrc,
                                               int bytes, uint64_t pol) {
    asm volatile("cp.async.cg.shared.global.L2::cache_hint [%0], [%1], 16, %2, %3;"
                 :: "r"(sdst), "l"(gsrc), "r"(bytes), "l"(pol));
}
__device__ __forceinline__ void cp_commit() {
    asm volatile("cp.async.commit_group;" ::: "memory");
}
__device__ __forceinline__ void cp_wait1() {
    asm volatile("cp.async.wait_group 1;" ::: "memory");
}
__device__ __forceinline__ void cp_wait0() {
    asm volatile("cp.async.wait_group 0;" ::: "memory");
}
__device__ __forceinline__ float4 ld_keep_f4(const float* p, uint64_t pol) {
    float4 v;
    asm volatile("ld.global.nc.L2::cache_hint.v4.f32 {%0,%1,%2,%3}, [%4], %5;"
                 : "=f"(v.x), "=f"(v.y), "=f"(v.z), "=f"(v.w)
                 : "l"(p), "l"(pol));
    return v;
}
__device__ __forceinline__ float4 ld_stream_f4(const float* p, uint64_t pol) {
    float4 v;
    asm volatile("ld.global.nc.L2::cache_hint.v4.f32 {%0,%1,%2,%3}, [%4], %5;"
                 : "=f"(v.x), "=f"(v.y), "=f"(v.z), "=f"(v.w)
                 : "l"(p), "l"(pol));
    return v;
}
__device__ __forceinline__ float sigmoidf_(float x) {
    return 1.0f / (1.0f + __expf(-x));
}
__device__ __forceinline__ void red_v4(float* p, float4 m) {
    asm volatile("red.global.add.v4.f32 [%0], {%1,%2,%3,%4};"
                 :: "l"(p), "f"(m.x), "f"(m.y), "f"(m.z), "f"(m.w));
}

struct GemmCtx { int wid, lane, g, t, wm, wn; };

// ===========================================================================
// Shared 128x128 K=128 tf32 GEMM body (R10-proven).
// ===========================================================================
__device__ __forceinline__
void gemm_body(const float* __restrict__ A, int M, int Wstride,
               const float* __restrict__ W, int colW0,
               int row0, char* smem, const GemmCtx& cx,
               float acc[2][8][4], uint64_t pol)
{
    uint32_t* Bs = (uint32_t*)smem;
    float* Abuf[2] = { (float*)(smem + B_BYTES),
                       (float*)(smem + B_BYTES + A_CHUNK_BYTES) };
    const uint32_t sbase = smem_u32(smem);
    const uint32_t a_s[2] = { sbase + B_BYTES, sbase + B_BYTES + A_CHUNK_BYTES };
    const int tid = threadIdx.x;

    auto copyA = [&](int chunk, uint32_t sdst) {
        #pragma unroll
        for (int j = 0; j < 4; j++) {
            const int idx = tid + j * 256;
            const int r   = idx >> 3;
            const int seg = idx & 7;
            const int gr  = row0 + r;
            const int bytes = (gr < M) ? 16 : 0;
            const int grc = (gr < M) ? gr : (M - 1);
            cp_async16_pol(sdst + (r * APAD + seg * 4) * 4,
                           A + (size_t)grc * 128 + chunk * KC + seg * 4, bytes, pol);
        }
    };

    copyA(0, a_s[0]); cp_commit();

    #pragma unroll
    for (int it = 0; it < 16; it++) {
        const int idx = tid + it * 256;
        const int k   = idx >> 5;
        const int n4  = (idx & 31) * 4;
        const float4 v = *(const float4*)&W[(size_t)k * Wstride + colW0 + n4];
        uint4 o;
        o.x = f2tf32(v.x); o.y = f2tf32(v.y); o.z = f2tf32(v.z); o.w = f2tf32(v.w);
        *(uint4*)&Bs[k * BPAD + n4] = o;
    }

    copyA(1, a_s[1]); cp_commit();

    #pragma unroll
    for (int m = 0; m < 2; m++)
        #pragma unroll
        for (int n = 0; n < 8; n++)
            #pragma unroll
            for (int j = 0; j < 4; j++) acc[m][n][j] = 0.f;

    auto compute_chunk = [&](const float* __restrict__ Ab, int kb) {
        #pragma unroll
        for (int ks = 0; ks < 4; ks++) {
            const int k0 = ks * 8;
            uint32_t af[2][4];
            #pragma unroll
            for (int m = 0; m < 2; m++) {
                const int rb = cx.wm * 32 + m * 16 + cx.g;
                const float* p0 = Ab + rb * APAD + k0 + cx.t;
                const float* p1 = Ab + (rb + 8) * APAD + k0 + cx.t;
                af[m][0] = f2tf32(p0[0]);
                af[m][1] = f2tf32(p1[0]);
                af[m][2] = f2tf32(p0[4]);
                af[m][3] = f2tf32(p1[4]);
            }
            #pragma unroll
            for (int n = 0; n < 8; n++) {
                const int nidx = cx.wn * 64 + n * 8 + cx.g;
                const uint32_t b0 = Bs[(kb + k0 + cx.t) * BPAD + nidx];
                const uint32_t b1 = Bs[(kb + k0 + cx.t + 4) * BPAD + nidx];
                #pragma unroll
                for (int m = 0; m < 2; m++)
                    mma_tf32(acc[m][n][0], acc[m][n][1], acc[m][n][2], acc[m][n][3],
                             af[m][0], af[m][1], af[m][2], af[m][3], b0, b1);
            }
        }
    };

    cp_wait1(); __syncthreads();
    compute_chunk(Abuf[0], 0);
    __syncthreads(); copyA(2, a_s[0]); cp_commit();

    cp_wait1(); __syncthreads();
    compute_chunk(Abuf[1], 32);
    __syncthreads(); copyA(3, a_s[1]); cp_commit();

    cp_wait1(); __syncthreads();
    compute_chunk(Abuf[0], 64);

    cp_wait0(); __syncthreads();
    compute_chunk(Abuf[1], 96);
}

// ===========================================================================
__global__ __launch_bounds__(256, 2)
void node_gemm(const float* __restrict__ nf,
               const float* __restrict__ Wk,
               const float* __restrict__ Wb,
               float* __restrict__ out,
               float* __restrict__ qkv)
{
    extern __shared__ char smem[];
    const int row0  = blockIdx.y * 128;
    const int colW0 = blockIdx.x * 128;
    const uint64_t pol = policy_evict_first();

    GemmCtx cx;
    {
        const int tid = threadIdx.x;
        cx.wid = tid >> 5; cx.lane = tid & 31;
        cx.g = cx.lane >> 2; cx.t = cx.lane & 3;
        cx.wm = cx.wid >> 1; cx.wn = cx.wid & 1;
    }
    float acc[2][8][4];
    gemm_body(nf, N_NODES, 512, Wk, colW0, row0, smem, cx, acc, pol);

    float2 bvs[8];
    #pragma unroll
    for (int n = 0; n < 8; n++)
        bvs[n] = *(const float2*)&Wb[colW0 + cx.wn * 64 + n * 8 + 2 * cx.t];

    float* C;
    int Cstride, colC0;
    if (blockIdx.x == 0) { C = out; Cstride = 128; colC0 = 0; }
    else                 { C = qkv; Cstride = 384; colC0 = colW0 - 128; }

    #pragma unroll
    for (int m = 0; m < 2; m++) {
        const int r0 = row0 + cx.wm * 32 + m * 16 + cx.g;
        const int r1 = r0 + 8;
        #pragma unroll
        for (int n = 0; n < 8; n++) {
            const int cc = colC0 + cx.wn * 64 + n * 8 + 2 * cx.t;
            if (r0 < N_NODES)
                *(float2*)&C[(size_t)r0 * Cstride + cc] =
                    make_float2(acc[m][n][0] + bvs[n].x, acc[m][n][1] + bvs[n].y);
            if (r1 < N_NODES)
                *(float2*)&C[(size_t)r1 * Cstride + cc] =
                    make_float2(acc[m][n][2] + bvs[n].x, acc[m][n][3] + bvs[n].y);
        }
    }
}

// ===========================================================================
// Edge projection chunk: ep[ebase : ebase+CHSZ] = ef @ We + be.
// Plain stores -> chunk stays L2-resident for the paired scatter.
// ===========================================================================
__global__ __launch_bounds__(256, 2)
void edge_gemm(const float* __restrict__ ef,
               const float* __restrict__ We,
               const float* __restrict__ Web,
               float* __restrict__ ep,
               int ebase)
{
    extern __shared__ char smem[];
    const int row0 = ebase + blockIdx.x * 128;
    const int Mhi  = ebase + CHSZ;                    // chunk bound (<= N_EDGES)
    const uint64_t pol = policy_evict_first();

    GemmCtx cx;
    {
        const int tid = threadIdx.x;
        cx.wid = tid >> 5; cx.lane = tid & 31;
        cx.g = cx.lane >> 2; cx.t = cx.lane & 3;
        cx.wm = cx.wid >> 1; cx.wn = cx.wid & 1;
    }
    float acc[2][8][4];
    gemm_body(ef, Mhi, 128, We, 0, row0, smem, cx, acc, pol);

    float2 bvs[8];
    #pragma unroll
    for (int n = 0; n < 8; n++)
        bvs[n] = *(const float2*)&Web[cx.wn * 64 + n * 8 + 2 * cx.t];

    #pragma unroll
    for (int m = 0; m < 2; m++) {
        const int r0 = row0 + cx.wm * 32 + m * 16 + cx.g;
        const int r1 = r0 + 8;
        #pragma unroll
        for (int n = 0; n < 8; n++) {
            const int cc = cx.wn * 64 + n * 8 + 2 * cx.t;
            if (r0 < Mhi)
                *(float2*)&ep[(size_t)r0 * 128 + cc] =
                    make_float2(acc[m][n][0] + bvs[n].x, acc[m][n][1] + bvs[n].y);
            if (r1 < Mhi)
                *(float2*)&ep[(size_t)r1 * 128 + cc] =
                    make_float2(acc[m][n][2] + bvs[n].x, acc[m][n][3] + bvs[n].y);
        }
    }
}

// ===========================================================================
// Scatter chunk: one warp per edge (high occupancy, RED-floor bound).
// ep read evict_first (read-once, frees L2); qkv pinned evict_last.
// ===========================================================================
__global__ __launch_bounds__(256)
void edge_scatter(const int* __restrict__ snd,
                  const int* __restrict__ rcv,
                  const float* __restrict__ qkv,
                  const float* __restrict__ ep,
                  float* __restrict__ out,
                  int ebase)
{
    const int wl   = (blockIdx.x * blockDim.x + threadIdx.x) >> 5;
    const int lane = threadIdx.x & 31;
    if (wl >= CHSZ) return;
    const int e = ebase + wl;

    const uint64_t pol_first = policy_evict_first();
    const uint64_t pol_keep  = policy_evict_last();

    const int s = __ldg(&snd[e]);
    const int r = __ldg(&rcv[e]);
    const int d = lane * 4;

    const float4 epv = ld_stream_f4(&ep[(size_t)e * 128 + d], pol_first);
    const float4 q   = ld_keep_f4(&qkv[(size_t)r * 384 + d], pol_keep);
    const float4 kk  = ld_keep_f4(&qkv[(size_t)s * 384 + 128 + d], pol_keep);
    const float4 v   = ld_keep_f4(&qkv[(size_t)s * 384 + 256 + d], pol_keep);

    float4 m;
    m.x = sigmoidf_(q.x + kk.x + epv.x) * v.x;
    m.y = sigmoidf_(q.y + kk.y + epv.y) * v.y;
    m.z = sigmoidf_(q.z + kk.z + epv.z) * v.z;
    m.w = sigmoidf_(q.w + kk.w + epv.w) * v.w;

    red_v4(&out[(size_t)r * 128 + d], m);
}

// ---------------------------------------------------------------------------
// Launch: fork/join two-stream graph.
// Inputs: 0 nf[50000,128] 1 snd[600000] 2 rcv[600000] 3 ef[600000,128]
//         4 Wk[128,512] 5 Wb[512] 6 Wek[128,128] 7 Web[128]
// ---------------------------------------------------------------------------
extern "C" void kernel_launch(void* const* d_in, const int* in_sizes, int n_in,
                              void* d_out, int out_size)
{
    const float* nf   = (const float*)d_in[0];
    const int*   snd  = (const int*)  d_in[1];
    const int*   rcv  = (const int*)  d_in[2];
    const float* ef   = (const float*)d_in[3];
    const float* Wk   = (const float*)d_in[4];
    const float* Wb   = (const float*)d_in[5];
    const float* Wek  = (const float*)d_in[6];
    const float* Web  = (const float*)d_in[7];
    float* out = (float*)d_out;

    float* qkv_ptr;
    float* ep_ptr;
    cudaGetSymbolAddress((void**)&qkv_ptr, g_qkv);
    cudaGetSymbolAddress((void**)&ep_ptr,  g_ep);

    static cudaStream_t s2 = nullptr;
    static cudaEvent_t evFork;
    static cudaEvent_t evG[CHUNKS];
    if (s2 == nullptr) {
        cudaStreamCreateWithFlags(&s2, cudaStreamNonBlocking);
        cudaEventCreateWithFlags(&evFork, cudaEventDisableTiming);
        for (int i = 0; i < CHUNKS; i++)
            cudaEventCreateWithFlags(&evG[i], cudaEventDisableTiming);
        cudaFuncSetAttribute(node_gemm,
                             cudaFuncAttributeMaxDynamicSharedMemorySize, GEMM_SMEM);
        cudaFuncSetAttribute(edge_gemm,
                             cudaFuncAttributeMaxDynamicSharedMemorySize, GEMM_SMEM);
    }

    // fork: s2 joins the capture after this event
    cudaEventRecord(evFork, 0);
    cudaStreamWaitEvent(s2, evFork, 0);

    // stream 0: node projection (h -> out, QKV -> g_qkv)
    {
        dim3 grid(4, (N_NODES + 127) / 128);
        node_gemm<<<grid, 256, GEMM_SMEM, 0>>>(nf, Wk, Wb, out, qkv_ptr);
    }

    // stream s2: edge projection chunks
    for (int i = 0; i < CHUNKS; i++) {
        const int blocks = (CHSZ + 127) / 128;
        edge_gemm<<<blocks, 256, GEMM_SMEM, s2>>>(ef, Wek, Web, ep_ptr, i * CHSZ);
        cudaEventRecord(evG[i], s2);
    }

    // stream 0: scatter chunks, each gated on its gemm chunk (joins s2 branch)
    for (int i = 0; i < CHUNKS; i++) {
        cudaStreamWaitEvent(0, evG[i], 0);
        const int blocks = (CHSZ * 32 + 255) / 256;
        edge_scatter<<<blocks, 256, 0, 0>>>(snd, rcv, qkv_ptr, ep_ptr, out, i * CHSZ);
    }
}

// round 14
// speedup vs baseline: 1.2701x; 1.2701x over previous
#include <cuda_runtime.h>
#include <cuda_bf16.h>
#include <cstdint>

// ---------------------------------------------------------------------------
// ResidualGatedGCN — node tf32 GEMM + fused edge GEMM/scatter (R10 base)
// Change vs R10: BPAD 132 -> 136 (B shared-memory loads become conflict-free:
// bank = 8t + g, a perfect lane permutation).
// ---------------------------------------------------------------------------

#define N_NODES 50000
#define N_EDGES 600000

__device__ float g_qkv[(size_t)N_NODES * 384];      // 76.8 MB

#define KC      32
#define APAD    36
#define BPAD    136
#define A_CHUNK_BYTES (128 * APAD * 4)   // 18432
#define B_BYTES       (128 * BPAD * 4)   // 69632
#define GEMM_SMEM     (B_BYTES + 2 * A_CHUNK_BYTES)        // 106496
#define FUSED_SMEM    (GEMM_SMEM + 2 * 128 * 4)

__device__ __forceinline__ uint32_t f2tf32(float f) {
    uint32_t u;
    asm("cvt.rna.tf32.f32 %0, %1;" : "=r"(u) : "f"(f));
    return u;
}
__device__ __forceinline__ void mma_tf32(float& d0, float& d1, float& d2, float& d3,
                                         uint32_t a0, uint32_t a1, uint32_t a2, uint32_t a3,
                                         uint32_t b0, uint32_t b1)
{
    asm volatile(
        "mma.sync.aligned.m16n8k8.row.col.f32.tf32.tf32.f32 "
        "{%0,%1,%2,%3}, {%4,%5,%6,%7}, {%8,%9}, {%0,%1,%2,%3};"
        : "+f"(d0), "+f"(d1), "+f"(d2), "+f"(d3)
        : "r"(a0), "r"(a1), "r"(a2), "r"(a3), "r"(b0), "r"(b1));
}
__device__ __forceinline__ uint32_t smem_u32(const void* p) {
    uint32_t a;
    asm("{ .reg .u64 t; cvta.to.shared.u64 t, %1; cvt.u32.u64 %0, t; }"
        : "=r"(a) : "l"(p));
    return a;
}
__device__ __forceinline__ uint64_t policy_evict_first() {
    uint64_t pol;
    asm("createpolicy.fractional.L2::evict_first.b64 %0, 1.0;" : "=l"(pol));
    return pol;
}
__device__ __forceinline__ uint64_t policy_evict_last() {
    uint64_t pol;
    asm("createpolicy.fractional.L2::evict_last.b64 %0, 1.0;" : "=l"(pol));
    return pol;
}
__device__ __forceinline__ void cp_async16_pol(uint32_t sdst, const void* gsrc,
                                               int bytes, uint64_t pol) {
    asm volatile("cp.async.cg.shared.global.L2::cache_hint [%0], [%1], 16, %2, %3;"
                 :: "r"(sdst), "l"(gsrc), "r"(bytes), "l"(pol));
}
__device__ __forceinline__ void cp_commit() {
    asm volatile("cp.async.commit_group;" ::: "memory");
}
__device__ __forceinline__ void cp_wait1() {
    asm volatile("cp.async.wait_group 1;" ::: "memory");
}
__device__ __forceinline__ void cp_wait0() {
    asm volatile("cp.async.wait_group 0;" ::: "memory");
}
__device__ __forceinline__ float4 ld_keep_f4(const float* p, uint64_t pol) {
    float4 v;
    asm volatile("ld.global.nc.L2::cache_hint.v4.f32 {%0,%1,%2,%3}, [%4], %5;"
                 : "=f"(v.x), "=f"(v.y), "=f"(v.z), "=f"(v.w)
                 : "l"(p), "l"(pol));
    return v;
}
__device__ __forceinline__ float sigmoidf_(float x) {
    return 1.0f / (1.0f + __expf(-x));
}
__device__ __forceinline__ void red_v4(float* p, float4 m) {
    asm volatile("red.global.add.v4.f32 [%0], {%1,%2,%3,%4};"
                 :: "l"(p), "f"(m.x), "f"(m.y), "f"(m.z), "f"(m.w));
}

struct GemmCtx { int wid, lane, g, t, wm, wn; };

// ===========================================================================
// Shared 128x128 K=128 tf32 GEMM body.
// ===========================================================================
__device__ __forceinline__
void gemm_body(const float* __restrict__ A, int M, int Wstride,
               const float* __restrict__ W, int colW0,
               int row0, char* smem, const GemmCtx& cx,
               float acc[2][8][4], uint64_t pol)
{
    uint32_t* Bs = (uint32_t*)smem;
    float* Abuf[2] = { (float*)(smem + B_BYTES),
                       (float*)(smem + B_BYTES + A_CHUNK_BYTES) };
    const uint32_t sbase = smem_u32(smem);
    const uint32_t a_s[2] = { sbase + B_BYTES, sbase + B_BYTES + A_CHUNK_BYTES };
    const int tid = threadIdx.x;

    auto copyA = [&](int chunk, uint32_t sdst) {
        #pragma unroll
        for (int j = 0; j < 4; j++) {
            const int idx = tid + j * 256;
            const int r   = idx >> 3;
            const int seg = idx & 7;
            const int gr  = row0 + r;
            const int bytes = (gr < M) ? 16 : 0;
            const int grc = (gr < M) ? gr : (M - 1);
            cp_async16_pol(sdst + (r * APAD + seg * 4) * 4,
                           A + (size_t)grc * 128 + chunk * KC + seg * 4, bytes, pol);
        }
    };

    copyA(0, a_s[0]); cp_commit();

    #pragma unroll
    for (int it = 0; it < 16; it++) {
        const int idx = tid + it * 256;
        const int k   = idx >> 5;
        const int n4  = (idx & 31) * 4;
        const float4 v = *(const float4*)&W[(size_t)k * Wstride + colW0 + n4];
        uint4 o;
        o.x = f2tf32(v.x); o.y = f2tf32(v.y); o.z = f2tf32(v.z); o.w = f2tf32(v.w);
        *(uint4*)&Bs[k * BPAD + n4] = o;
    }

    copyA(1, a_s[1]); cp_commit();

    #pragma unroll
    for (int m = 0; m < 2; m++)
        #pragma unroll
        for (int n = 0; n < 8; n++)
            #pragma unroll
            for (int j = 0; j < 4; j++) acc[m][n][j] = 0.f;

    auto compute_chunk = [&](const float* __restrict__ Ab, int kb) {
        #pragma unroll
        for (int ks = 0; ks < 4; ks++) {
            const int k0 = ks * 8;
            uint32_t af[2][4];
            #pragma unroll
            for (int m = 0; m < 2; m++) {
                const int rb = cx.wm * 32 + m * 16 + cx.g;
                const float* p0 = Ab + rb * APAD + k0 + cx.t;
                const float* p1 = Ab + (rb + 8) * APAD + k0 + cx.t;
                af[m][0] = f2tf32(p0[0]);
                af[m][1] = f2tf32(p1[0]);
                af[m][2] = f2tf32(p0[4]);
                af[m][3] = f2tf32(p1[4]);
            }
            #pragma unroll
            for (int n = 0; n < 8; n++) {
                const int nidx = cx.wn * 64 + n * 8 + cx.g;
                const uint32_t b0 = Bs[(kb + k0 + cx.t) * BPAD + nidx];
                const uint32_t b1 = Bs[(kb + k0 + cx.t + 4) * BPAD + nidx];
                #pragma unroll
                for (int m = 0; m < 2; m++)
                    mma_tf32(acc[m][n][0], acc[m][n][1], acc[m][n][2], acc[m][n][3],
                             af[m][0], af[m][1], af[m][2], af[m][3], b0, b1);
            }
        }
    };

    cp_wait1(); __syncthreads();
    compute_chunk(Abuf[0], 0);
    __syncthreads(); copyA(2, a_s[0]); cp_commit();

    cp_wait1(); __syncthreads();
    compute_chunk(Abuf[1], 32);
    __syncthreads(); copyA(3, a_s[1]); cp_commit();

    cp_wait1(); __syncthreads();
    compute_chunk(Abuf[0], 64);

    cp_wait0(); __syncthreads();
    compute_chunk(Abuf[1], 96);
}

// ===========================================================================
__global__ __launch_bounds__(256, 2)
void node_gemm(const float* __restrict__ nf,
               const float* __restrict__ Wk,
               const float* __restrict__ Wb,
               float* __restrict__ out,
               float* __restrict__ qkv)
{
    extern __shared__ char smem[];
    const int row0  = blockIdx.y * 128;
    const int colW0 = blockIdx.x * 128;
    const uint64_t pol = policy_evict_first();

    GemmCtx cx;
    {
        const int tid = threadIdx.x;
        cx.wid = tid >> 5; cx.lane = tid & 31;
        cx.g = cx.lane >> 2; cx.t = cx.lane & 3;
        cx.wm = cx.wid >> 1; cx.wn = cx.wid & 1;
    }
    float acc[2][8][4];
    gemm_body(nf, N_NODES, 512, Wk, colW0, row0, smem, cx, acc, pol);

    float2 bvs[8];
    #pragma unroll
    for (int n = 0; n < 8; n++)
        bvs[n] = *(const float2*)&Wb[colW0 + cx.wn * 64 + n * 8 + 2 * cx.t];

    float* C;
    int Cstride, colC0;
    if (blockIdx.x == 0) { C = out; Cstride = 128; colC0 = 0; }
    else                 { C = qkv; Cstride = 384; colC0 = colW0 - 128; }

    #pragma unroll
    for (int m = 0; m < 2; m++) {
        const int r0 = row0 + cx.wm * 32 + m * 16 + cx.g;
        const int r1 = r0 + 8;
        #pragma unroll
        for (int n = 0; n < 8; n++) {
            const int cc = colC0 + cx.wn * 64 + n * 8 + 2 * cx.t;
            if (r0 < N_NODES)
                *(float2*)&C[(size_t)r0 * Cstride + cc] =
                    make_float2(acc[m][n][0] + bvs[n].x, acc[m][n][1] + bvs[n].y);
            if (r1 < N_NODES)
                *(float2*)&C[(size_t)r1 * Cstride + cc] =
                    make_float2(acc[m][n][2] + bvs[n].x, acc[m][n][3] + bvs[n].y);
        }
    }
}

// ===========================================================================
__global__ __launch_bounds__(256, 2)
void edge_fused(const float* __restrict__ ef,
                const float* __restrict__ We,
                const float* __restrict__ Web,
                const int*   __restrict__ snd,
                const int*   __restrict__ rcv,
                const float* __restrict__ qkv,
                float* __restrict__ out)
{
    extern __shared__ char smem[];
    float* ep_s  = (float*)smem;                  // reuses B region post-MMA
    int*   s_snd = (int*)(smem + GEMM_SMEM);
    int*   s_rcv = (int*)(smem + GEMM_SMEM + 128 * 4);

    const int tid  = threadIdx.x;
    const int row0 = blockIdx.x * 128;
    const uint64_t pol_stream = policy_evict_first();
    const uint64_t pol_keep   = policy_evict_last();

    if (tid < 128) {
        const int e = row0 + tid;
        s_snd[tid] = (e < N_EDGES) ? __ldg(&snd[e]) : 0;
    } else {
        const int e = row0 + tid - 128;
        s_rcv[tid - 128] = (e < N_EDGES) ? __ldg(&rcv[e]) : 0;
    }

    GemmCtx cx;
    cx.wid = tid >> 5; cx.lane = tid & 31;
    cx.g = cx.lane >> 2; cx.t = cx.lane & 3;
    cx.wm = cx.wid >> 1; cx.wn = cx.wid & 1;

    float acc[2][8][4];
    gemm_body(ef, N_EDGES, 128, We, 0, row0, smem, cx, acc, pol_stream);

    // ---- park ep (+bias) into SMEM (B region dead after last chunk) ----
    __syncthreads();
    float2 bvs[8];
    #pragma unroll
    for (int n = 0; n < 8; n++)
        bvs[n] = *(const float2*)&Web[cx.wn * 64 + n * 8 + 2 * cx.t];

    #pragma unroll
    for (int m = 0; m < 2; m++) {
        const int r0l = cx.wm * 32 + m * 16 + cx.g;
        #pragma unroll
        for (int n = 0; n < 8; n++) {
            const int cc = cx.wn * 64 + n * 8 + 2 * cx.t;
            *(float2*)&ep_s[r0l * BPAD + cc] =
                make_float2(acc[m][n][0] + bvs[n].x, acc[m][n][1] + bvs[n].y);
            *(float2*)&ep_s[(r0l + 8) * BPAD + cc] =
                make_float2(acc[m][n][2] + bvs[n].x, acc[m][n][3] + bvs[n].y);
        }
    }
    __syncthreads();

    // ---- phase C: 4-edge ILP batches, warp-coherent ld.v4/red.v4 ----
    const int d = cx.lane * 4;
    #pragma unroll
    for (int b = 0; b < 4; b++) {
        int el[4], ss[4], rr[4];
        bool ok[4];
        #pragma unroll
        for (int i = 0; i < 4; i++) {
            el[i] = cx.wid * 16 + b * 4 + i;
            ok[i] = (row0 + el[i]) < N_EDGES;
            ss[i] = s_snd[el[i]];
            rr[i] = s_rcv[el[i]];
        }
        float4 q[4], kk[4], vv[4], epv[4];
        #pragma unroll
        for (int i = 0; i < 4; i++) {
            q[i]   = ld_keep_f4(&qkv[(size_t)rr[i] * 384 + d], pol_keep);
            kk[i]  = ld_keep_f4(&qkv[(size_t)ss[i] * 384 + 128 + d], pol_keep);
            vv[i]  = ld_keep_f4(&qkv[(size_t)ss[i] * 384 + 256 + d], pol_keep);
            epv[i] = *(const float4*)&ep_s[el[i] * BPAD + d];
        }
        #pragma unroll
        for (int i = 0; i < 4; i++) {
            float4 m;
            m.x = sigmoidf_(q[i].x + kk[i].x + epv[i].x) * vv[i].x;
            m.y = sigmoidf_(q[i].y + kk[i].y + epv[i].y) * vv[i].y;
            m.z = sigmoidf_(q[i].z + kk[i].z + epv[i].z) * vv[i].z;
            m.w = sigmoidf_(q[i].w + kk[i].w + epv[i].w) * vv[i].w;
            if (ok[i])
                red_v4(&out[(size_t)rr[i] * 128 + d], m);
        }
    }
}

// ---------------------------------------------------------------------------
// Launch
// Inputs: 0 nf[50000,128] 1 snd[600000] 2 rcv[600000] 3 ef[600000,128]
//         4 Wk[128,512] 5 Wb[512] 6 Wek[128,128] 7 Web[128]
// ---------------------------------------------------------------------------
extern "C" void kernel_launch(void* const* d_in, const int* in_sizes, int n_in,
                              void* d_out, int out_size)
{
    const float* nf   = (const float*)d_in[0];
    const int*   snd  = (const int*)  d_in[1];
    const int*   rcv  = (const int*)  d_in[2];
    const float* ef   = (const float*)d_in[3];
    const float* Wk   = (const float*)d_in[4];
    const float* Wb   = (const float*)d_in[5];
    const float* Wek  = (const float*)d_in[6];
    const float* Web  = (const float*)d_in[7];
    float* out = (float*)d_out;

    float* qkv_ptr;
    cudaGetSymbolAddress((void**)&qkv_ptr, g_qkv);

    cudaFuncSetAttribute(node_gemm,
                         cudaFuncAttributeMaxDynamicSharedMemorySize, GEMM_SMEM);
    cudaFuncSetAttribute(edge_fused,
                         cudaFuncAttributeMaxDynamicSharedMemorySize, FUSED_SMEM);

    {
        dim3 grid(4, (N_NODES + 127) / 128);
        node_gemm<<<grid, 256, GEMM_SMEM>>>(nf, Wk, Wb, out, qkv_ptr);
    }
    {
        int blocks = (N_EDGES + 127) / 128;
        edge_fused<<<blocks, 256, FUSED_SMEM>>>(ef, Wek, Web, snd, rcv, qkv_ptr, out);
    }
}

// round 15
// speedup vs baseline: 1.2820x; 1.0094x over previous
#include <cuda_runtime.h>
#include <cuda_bf16.h>
#include <cstdint>

// ---------------------------------------------------------------------------
// ResidualGatedGCN — node tf32 GEMM + fused edge GEMM/scatter
// R15: each 256-thread CTA split into two independent 128-thread halves
// (own cp.async groups + named barriers) so the halves drift and hide each
// other's memory latency. Full-CTA syncs only at true cross-half points.
// ---------------------------------------------------------------------------

#define N_NODES 50000
#define N_EDGES 600000

__device__ float g_qkv[(size_t)N_NODES * 384];      // 76.8 MB

#define KC      32
#define APAD    36
#define BPAD    136
#define A_CHUNK_BYTES (128 * APAD * 4)   // 18432 (full 128 rows; halves own 64 each)
#define B_BYTES       (128 * BPAD * 4)   // 69632
#define GEMM_SMEM     (B_BYTES + 2 * A_CHUNK_BYTES)        // 106496
#define FUSED_SMEM    (GEMM_SMEM + 2 * 128 * 4)

__device__ __forceinline__ uint32_t f2tf32(float f) {
    uint32_t u;
    asm("cvt.rna.tf32.f32 %0, %1;" : "=r"(u) : "f"(f));
    return u;
}
__device__ __forceinline__ void mma_tf32(float& d0, float& d1, float& d2, float& d3,
                                         uint32_t a0, uint32_t a1, uint32_t a2, uint32_t a3,
                                         uint32_t b0, uint32_t b1)
{
    asm volatile(
        "mma.sync.aligned.m16n8k8.row.col.f32.tf32.tf32.f32 "
        "{%0,%1,%2,%3}, {%4,%5,%6,%7}, {%8,%9}, {%0,%1,%2,%3};"
        : "+f"(d0), "+f"(d1), "+f"(d2), "+f"(d3)
        : "r"(a0), "r"(a1), "r"(a2), "r"(a3), "r"(b0), "r"(b1));
}
__device__ __forceinline__ uint32_t smem_u32(const void* p) {
    uint32_t a;
    asm("{ .reg .u64 t; cvta.to.shared.u64 t, %1; cvt.u32.u64 %0, t; }"
        : "=r"(a) : "l"(p));
    return a;
}
__device__ __forceinline__ uint64_t policy_evict_first() {
    uint64_t pol;
    asm("createpolicy.fractional.L2::evict_first.b64 %0, 1.0;" : "=l"(pol));
    return pol;
}
__device__ __forceinline__ uint64_t policy_evict_last() {
    uint64_t pol;
    asm("createpolicy.fractional.L2::evict_last.b64 %0, 1.0;" : "=l"(pol));
    return pol;
}
__device__ __forceinline__ void cp_async16_pol(uint32_t sdst, const void* gsrc,
                                               int bytes, uint64_t pol) {
    asm volatile("cp.async.cg.shared.global.L2::cache_hint [%0], [%1], 16, %2, %3;"
                 :: "r"(sdst), "l"(gsrc), "r"(bytes), "l"(pol));
}
__device__ __forceinline__ void cp_commit() {
    asm volatile("cp.async.commit_group;" ::: "memory");
}
__device__ __forceinline__ void cp_wait1() {
    asm volatile("cp.async.wait_group 1;" ::: "memory");
}
__device__ __forceinline__ void cp_wait0() {
    asm volatile("cp.async.wait_group 0;" ::: "memory");
}
// per-half barrier: id 1 or 2, 128 threads
__device__ __forceinline__ void half_sync(int half) {
    asm volatile("bar.sync %0, 128;" :: "r"(half + 1) : "memory");
}
__device__ __forceinline__ float4 ld_keep_f4(const float* p, uint64_t pol) {
    float4 v;
    asm volatile("ld.global.nc.L2::cache_hint.v4.f32 {%0,%1,%2,%3}, [%4], %5;"
                 : "=f"(v.x), "=f"(v.y), "=f"(v.z), "=f"(v.w)
                 : "l"(p), "l"(pol));
    return v;
}
__device__ __forceinline__ float sigmoidf_(float x) {
    return 1.0f / (1.0f + __expf(-x));
}
__device__ __forceinline__ void red_v4(float* p, float4 m) {
    asm volatile("red.global.add.v4.f32 [%0], {%1,%2,%3,%4};"
                 :: "l"(p), "f"(m.x), "f"(m.y), "f"(m.z), "f"(m.w));
}

struct GemmCtx { int wid, lane, g, t, wm, wn, half, htid; };

// ===========================================================================
// Split-half 128x128 K=128 tf32 GEMM body.
// Half h (threads 128h..128h+127, warps with wm in {2h,2h+1}) owns A rows
// 64h..64h+63: its own cp.async chunks and named barrier. B staged by the
// full CTA once (caller provides the __syncthreads after staging).
// ===========================================================================
__device__ __forceinline__
void gemm_body(const float* __restrict__ A, int M, int Wstride,
               const float* __restrict__ W, int colW0,
               int row0, char* smem, const GemmCtx& cx,
               float acc[2][8][4], uint64_t pol)
{
    uint32_t* Bs = (uint32_t*)smem;
    float* Abuf[2] = { (float*)(smem + B_BYTES),
                       (float*)(smem + B_BYTES + A_CHUNK_BYTES) };
    const uint32_t sbase = smem_u32(smem);
    const uint32_t a_s[2] = { sbase + B_BYTES, sbase + B_BYTES + A_CHUNK_BYTES };
    const int tid = threadIdx.x;

    // per-half A chunk copy: 64 rows x 32 floats = 512 x 16B segs / 128 thr
    auto copyA = [&](int chunk, uint32_t sdst) {
        #pragma unroll
        for (int j = 0; j < 4; j++) {
            const int idx = cx.htid + j * 128;      // 0..511 within half
            const int r   = cx.half * 64 + (idx >> 3);
            const int seg = idx & 7;
            const int gr  = row0 + r;
            const int bytes = (gr < M) ? 16 : 0;
            const int grc = (gr < M) ? gr : (M - 1);
            cp_async16_pol(sdst + (r * APAD + seg * 4) * 4,
                           A + (size_t)grc * 128 + chunk * KC + seg * 4, bytes, pol);
        }
    };

    copyA(0, a_s[0]); cp_commit();

    // ---- stage B (full CTA) ----
    #pragma unroll
    for (int it = 0; it < 16; it++) {
        const int idx = tid + it * 256;
        const int k   = idx >> 5;
        const int n4  = (idx & 31) * 4;
        const float4 v = *(const float4*)&W[(size_t)k * Wstride + colW0 + n4];
        uint4 o;
        o.x = f2tf32(v.x); o.y = f2tf32(v.y); o.z = f2tf32(v.z); o.w = f2tf32(v.w);
        *(uint4*)&Bs[k * BPAD + n4] = o;
    }

    copyA(1, a_s[1]); cp_commit();

    #pragma unroll
    for (int m = 0; m < 2; m++)
        #pragma unroll
        for (int n = 0; n < 8; n++)
            #pragma unroll
            for (int j = 0; j < 4; j++) acc[m][n][j] = 0.f;

    auto compute_chunk = [&](const float* __restrict__ Ab, int kb) {
        #pragma unroll
        for (int ks = 0; ks < 4; ks++) {
            const int k0 = ks * 8;
            uint32_t af[2][4];
            #pragma unroll
            for (int m = 0; m < 2; m++) {
                const int rb = cx.wm * 32 + m * 16 + cx.g;
                const float* p0 = Ab + rb * APAD + k0 + cx.t;
                const float* p1 = Ab + (rb + 8) * APAD + k0 + cx.t;
                af[m][0] = f2tf32(p0[0]);
                af[m][1] = f2tf32(p1[0]);
                af[m][2] = f2tf32(p0[4]);
                af[m][3] = f2tf32(p1[4]);
            }
            #pragma unroll
            for (int n = 0; n < 8; n++) {
                const int nidx = cx.wn * 64 + n * 8 + cx.g;
                const uint32_t b0 = Bs[(kb + k0 + cx.t) * BPAD + nidx];
                const uint32_t b1 = Bs[(kb + k0 + cx.t + 4) * BPAD + nidx];
                #pragma unroll
                for (int m = 0; m < 2; m++)
                    mma_tf32(acc[m][n][0], acc[m][n][1], acc[m][n][2], acc[m][n][3],
                             af[m][0], af[m][1], af[m][2], af[m][3], b0, b1);
            }
        }
    };

    // B visible to all + chunk0/1 committed; after this, halves run free.
    cp_wait1();
    __syncthreads();

    // ---- per-half pipelined chunks ----
    compute_chunk(Abuf[0], 0);
    half_sync(cx.half);                      // half done reading its Abuf[0] rows
    copyA(2, a_s[0]); cp_commit();

    cp_wait1(); half_sync(cx.half);
    compute_chunk(Abuf[1], 32);
    half_sync(cx.half);
    copyA(3, a_s[1]); cp_commit();

    cp_wait1(); half_sync(cx.half);
    compute_chunk(Abuf[0], 64);

    cp_wait0(); half_sync(cx.half);
    compute_chunk(Abuf[1], 96);
}

__device__ __forceinline__ GemmCtx make_ctx() {
    GemmCtx cx;
    const int tid = threadIdx.x;
    cx.wid = tid >> 5; cx.lane = tid & 31;
    cx.g = cx.lane >> 2; cx.t = cx.lane & 3;
    cx.wm = cx.wid >> 1; cx.wn = cx.wid & 1;
    cx.half = tid >> 7;          // warps 0-3 -> half0 (rows 0-63), 4-7 -> half1
    cx.htid = tid & 127;
    return cx;
}

// ===========================================================================
__global__ __launch_bounds__(256, 2)
void node_gemm(const float* __restrict__ nf,
               const float* __restrict__ Wk,
               const float* __restrict__ Wb,
               float* __restrict__ out,
               float* __restrict__ qkv)
{
    extern __shared__ char smem[];
    const int row0  = blockIdx.y * 128;
    const int colW0 = blockIdx.x * 128;
    const uint64_t pol = policy_evict_first();

    GemmCtx cx = make_ctx();
    float acc[2][8][4];
    gemm_body(nf, N_NODES, 512, Wk, colW0, row0, smem, cx, acc, pol);

    float2 bvs[8];
    #pragma unroll
    for (int n = 0; n < 8; n++)
        bvs[n] = *(const float2*)&Wb[colW0 + cx.wn * 64 + n * 8 + 2 * cx.t];

    float* C;
    int Cstride, colC0;
    if (blockIdx.x == 0) { C = out; Cstride = 128; colC0 = 0; }
    else                 { C = qkv; Cstride = 384; colC0 = colW0 - 128; }

    #pragma unroll
    for (int m = 0; m < 2; m++) {
        const int r0 = row0 + cx.wm * 32 + m * 16 + cx.g;
        const int r1 = r0 + 8;
        #pragma unroll
        for (int n = 0; n < 8; n++) {
            const int cc = colC0 + cx.wn * 64 + n * 8 + 2 * cx.t;
            if (r0 < N_NODES)
                *(float2*)&C[(size_t)r0 * Cstride + cc] =
                    make_float2(acc[m][n][0] + bvs[n].x, acc[m][n][1] + bvs[n].y);
            if (r1 < N_NODES)
                *(float2*)&C[(size_t)r1 * Cstride + cc] =
                    make_float2(acc[m][n][2] + bvs[n].x, acc[m][n][3] + bvs[n].y);
        }
    }
}

// ===========================================================================
__global__ __launch_bounds__(256, 2)
void edge_fused(const float* __restrict__ ef,
                const float* __restrict__ We,
                const float* __restrict__ Web,
                const int*   __restrict__ snd,
                const int*   __restrict__ rcv,
                const float* __restrict__ qkv,
                float* __restrict__ out)
{
    extern __shared__ char smem[];
    float* ep_s  = (float*)smem;                  // reuses B region post-MMA
    int*   s_snd = (int*)(smem + GEMM_SMEM);
    int*   s_rcv = (int*)(smem + GEMM_SMEM + 128 * 4);

    const int tid  = threadIdx.x;
    const int row0 = blockIdx.x * 128;
    const uint64_t pol_stream = policy_evict_first();
    const uint64_t pol_keep   = policy_evict_last();

    if (tid < 128) {
        const int e = row0 + tid;
        s_snd[tid] = (e < N_EDGES) ? __ldg(&snd[e]) : 0;
    } else {
        const int e = row0 + tid - 128;
        s_rcv[tid - 128] = (e < N_EDGES) ? __ldg(&rcv[e]) : 0;
    }

    GemmCtx cx = make_ctx();
    float acc[2][8][4];
    gemm_body(ef, N_EDGES, 128, We, 0, row0, smem, cx, acc, pol_stream);

    // ---- full-CTA join: everyone done reading Bs; park ep (+bias) ----
    __syncthreads();
    float2 bvs[8];
    #pragma unroll
    for (int n = 0; n < 8; n++)
        bvs[n] = *(const float2*)&Web[cx.wn * 64 + n * 8 + 2 * cx.t];

    #pragma unroll
    for (int m = 0; m < 2; m++) {
        const int r0l = cx.wm * 32 + m * 16 + cx.g;
        #pragma unroll
        for (int n = 0; n < 8; n++) {
            const int cc = cx.wn * 64 + n * 8 + 2 * cx.t;
            *(float2*)&ep_s[r0l * BPAD + cc] =
                make_float2(acc[m][n][0] + bvs[n].x, acc[m][n][1] + bvs[n].y);
            *(float2*)&ep_s[(r0l + 8) * BPAD + cc] =
                make_float2(acc[m][n][2] + bvs[n].x, acc[m][n][3] + bvs[n].y);
        }
    }
    __syncthreads();

    // ---- phase C: 4-edge ILP batches, warp-coherent ld.v4/red.v4 ----
    const int d = cx.lane * 4;
    #pragma unroll
    for (int b = 0; b < 4; b++) {
        int el[4], ss[4], rr[4];
        bool ok[4];
        #pragma unroll
        for (int i = 0; i < 4; i++) {
            el[i] = cx.wid * 16 + b * 4 + i;
            ok[i] = (row0 + el[i]) < N_EDGES;
            ss[i] = s_snd[el[i]];
            rr[i] = s_rcv[el[i]];
        }
        float4 q[4], kk[4], vv[4], epv[4];
        #pragma unroll
        for (int i = 0; i < 4; i++) {
            q[i]   = ld_keep_f4(&qkv[(size_t)rr[i] * 384 + d], pol_keep);
            kk[i]  = ld_keep_f4(&qkv[(size_t)ss[i] * 384 + 128 + d], pol_keep);
            vv[i]  = ld_keep_f4(&qkv[(size_t)ss[i] * 384 + 256 + d], pol_keep);
            epv[i] = *(const float4*)&ep_s[el[i] * BPAD + d];
        }
        #pragma unroll
        for (int i = 0; i < 4; i++) {
            float4 m;
            m.x = sigmoidf_(q[i].x + kk[i].x + epv[i].x) * vv[i].x;
            m.y = sigmoidf_(q[i].y + kk[i].y + epv[i].y) * vv[i].y;
            m.z = sigmoidf_(q[i].z + kk[i].z + epv[i].z) * vv[i].z;
            m.w = sigmoidf_(q[i].w + kk[i].w + epv[i].w) * vv[i].w;
            if (ok[i])
                red_v4(&out[(size_t)rr[i] * 128 + d], m);
        }
    }
}

// ---------------------------------------------------------------------------
// Launch
// Inputs: 0 nf[50000,128] 1 snd[600000] 2 rcv[600000] 3 ef[600000,128]
//         4 Wk[128,512] 5 Wb[512] 6 Wek[128,128] 7 Web[128]
// ---------------------------------------------------------------------------
extern "C" void kernel_launch(void* const* d_in, const int* in_sizes, int n_in,
                              void* d_out, int out_size)
{
    const float* nf   = (const float*)d_in[0];
    const int*   snd  = (const int*)  d_in[1];
    const int*   rcv  = (const int*)  d_in[2];
    const float* ef   = (const float*)d_in[3];
    const float* Wk   = (const float*)d_in[4];
    const float* Wb   = (const float*)d_in[5];
    const float* Wek  = (const float*)d_in[6];
    const float* Web  = (const float*)d_in[7];
    float* out = (float*)d_out;

    float* qkv_ptr;
    cudaGetSymbolAddress((void**)&qkv_ptr, g_qkv);

    cudaFuncSetAttribute(node_gemm,
                         cudaFuncAttributeMaxDynamicSharedMemorySize, GEMM_SMEM);
    cudaFuncSetAttribute(edge_fused,
                         cudaFuncAttributeMaxDynamicSharedMemorySize, FUSED_SMEM);

    {
        dim3 grid(4, (N_NODES + 127) / 128);
        node_gemm<<<grid, 256, GEMM_SMEM>>>(nf, Wk, Wb, out, qkv_ptr);
    }
    {
        int blocks = (N_EDGES + 127) / 128;
        edge_fused<<<blocks, 256, FUSED_SMEM>>>(ef, Wek, Web, snd, rcv, qkv_ptr, out);
    }
}

// round 16
// speedup vs baseline: 1.2841x; 1.0017x over previous
#include <cuda_runtime.h>
#include <cuda_bf16.h>
#include <cstdint>

// ---------------------------------------------------------------------------
// ResidualGatedGCN — SINGLE fused kernel.
//   Tiles 0..NODE_TILES-1  : node projection (h -> out, QKV -> g_qkv)
//   Tiles NODE_TILES..     : edge tiles: ep GEMM (SMEM) -> gate on node
//                            completion -> gather/sigmoid/red phase C.
// Node GEMM overlaps edge GEMM instead of running serially.
// ---------------------------------------------------------------------------

#define N_NODES 50000
#define N_EDGES 600000
#define NODE_TILES 1564                    // 391 row-tiles x 4 col-tiles
#define EDGE_TILES 4688                    // ceil(600000/128)
#define ALL_TILES  (NODE_TILES + EDGE_TILES)

__device__ float g_qkv[(size_t)N_NODES * 384];      // 76.8 MB
__device__ unsigned g_node_done = 0;
__device__ unsigned g_edge_done = 0;

#define KC      32
#define APAD    36
#define BPAD    136
#define A_CHUNK_BYTES (128 * APAD * 4)   // 18432
#define B_BYTES       (128 * BPAD * 4)   // 69632
#define GEMM_SMEM     (B_BYTES + 2 * A_CHUNK_BYTES)        // 106496
#define FUSED_SMEM    (GEMM_SMEM + 2 * 128 * 4)

__device__ __forceinline__ uint32_t f2tf32(float f) {
    uint32_t u;
    asm("cvt.rna.tf32.f32 %0, %1;" : "=r"(u) : "f"(f));
    return u;
}
__device__ __forceinline__ void mma_tf32(float& d0, float& d1, float& d2, float& d3,
                                         uint32_t a0, uint32_t a1, uint32_t a2, uint32_t a3,
                                         uint32_t b0, uint32_t b1)
{
    asm volatile(
        "mma.sync.aligned.m16n8k8.row.col.f32.tf32.tf32.f32 "
        "{%0,%1,%2,%3}, {%4,%5,%6,%7}, {%8,%9}, {%0,%1,%2,%3};"
        : "+f"(d0), "+f"(d1), "+f"(d2), "+f"(d3)
        : "r"(a0), "r"(a1), "r"(a2), "r"(a3), "r"(b0), "r"(b1));
}
__device__ __forceinline__ uint32_t smem_u32(const void* p) {
    uint32_t a;
    asm("{ .reg .u64 t; cvta.to.shared.u64 t, %1; cvt.u32.u64 %0, t; }"
        : "=r"(a) : "l"(p));
    return a;
}
__device__ __forceinline__ uint64_t policy_evict_first() {
    uint64_t pol;
    asm("createpolicy.fractional.L2::evict_first.b64 %0, 1.0;" : "=l"(pol));
    return pol;
}
__device__ __forceinline__ uint64_t policy_evict_last() {
    uint64_t pol;
    asm("createpolicy.fractional.L2::evict_last.b64 %0, 1.0;" : "=l"(pol));
    return pol;
}
__device__ __forceinline__ void cp_async16_pol(uint32_t sdst, const void* gsrc,
                                               int bytes, uint64_t pol) {
    asm volatile("cp.async.cg.shared.global.L2::cache_hint [%0], [%1], 16, %2, %3;"
                 :: "r"(sdst), "l"(gsrc), "r"(bytes), "l"(pol));
}
__device__ __forceinline__ void cp_commit() {
    asm volatile("cp.async.commit_group;" ::: "memory");
}
__device__ __forceinline__ void cp_wait1() {
    asm volatile("cp.async.wait_group 1;" ::: "memory");
}
__device__ __forceinline__ void cp_wait0() {
    asm volatile("cp.async.wait_group 0;" ::: "memory");
}
__device__ __forceinline__ void half_sync(int half) {
    asm volatile("bar.sync %0, 128;" :: "r"(half + 1) : "memory");
}
__device__ __forceinline__ float4 ld_keep_f4(const float* p, uint64_t pol) {
    float4 v;
    asm volatile("ld.global.nc.L2::cache_hint.v4.f32 {%0,%1,%2,%3}, [%4], %5;"
                 : "=f"(v.x), "=f"(v.y), "=f"(v.z), "=f"(v.w)
                 : "l"(p), "l"(pol));
    return v;
}
__device__ __forceinline__ float sigmoidf_(float x) {
    return 1.0f / (1.0f + __expf(-x));
}
__device__ __forceinline__ void red_v4(float* p, float4 m) {
    asm volatile("red.global.add.v4.f32 [%0], {%1,%2,%3,%4};"
                 :: "l"(p), "f"(m.x), "f"(m.y), "f"(m.z), "f"(m.w));
}

struct GemmCtx { int wid, lane, g, t, wm, wn, half, htid; };

__device__ __forceinline__ GemmCtx make_ctx() {
    GemmCtx cx;
    const int tid = threadIdx.x;
    cx.wid = tid >> 5; cx.lane = tid & 31;
    cx.g = cx.lane >> 2; cx.t = cx.lane & 3;
    cx.wm = cx.wid >> 1; cx.wn = cx.wid & 1;
    cx.half = tid >> 7;
    cx.htid = tid & 127;
    return cx;
}

// ===========================================================================
// Split-half 128x128 K=128 tf32 GEMM body (R15-proven).
// ===========================================================================
__device__ __forceinline__
void gemm_body(const float* __restrict__ A, int M, int Wstride,
               const float* __restrict__ W, int colW0,
               int row0, char* smem, const GemmCtx& cx,
               float acc[2][8][4], uint64_t pol)
{
    uint32_t* Bs = (uint32_t*)smem;
    float* Abuf[2] = { (float*)(smem + B_BYTES),
                       (float*)(smem + B_BYTES + A_CHUNK_BYTES) };
    const uint32_t sbase = smem_u32(smem);
    const uint32_t a_s[2] = { sbase + B_BYTES, sbase + B_BYTES + A_CHUNK_BYTES };
    const int tid = threadIdx.x;

    auto copyA = [&](int chunk, uint32_t sdst) {
        #pragma unroll
        for (int j = 0; j < 4; j++) {
            const int idx = cx.htid + j * 128;
            const int r   = cx.half * 64 + (idx >> 3);
            const int seg = idx & 7;
            const int gr  = row0 + r;
            const int bytes = (gr < M) ? 16 : 0;
            const int grc = (gr < M) ? gr : (M - 1);
            cp_async16_pol(sdst + (r * APAD + seg * 4) * 4,
                           A + (size_t)grc * 128 + chunk * KC + seg * 4, bytes, pol);
        }
    };

    copyA(0, a_s[0]); cp_commit();

    #pragma unroll
    for (int it = 0; it < 16; it++) {
        const int idx = tid + it * 256;
        const int k   = idx >> 5;
        const int n4  = (idx & 31) * 4;
        const float4 v = *(const float4*)&W[(size_t)k * Wstride + colW0 + n4];
        uint4 o;
        o.x = f2tf32(v.x); o.y = f2tf32(v.y); o.z = f2tf32(v.z); o.w = f2tf32(v.w);
        *(uint4*)&Bs[k * BPAD + n4] = o;
    }

    copyA(1, a_s[1]); cp_commit();

    #pragma unroll
    for (int m = 0; m < 2; m++)
        #pragma unroll
        for (int n = 0; n < 8; n++)
            #pragma unroll
            for (int j = 0; j < 4; j++) acc[m][n][j] = 0.f;

    auto compute_chunk = [&](const float* __restrict__ Ab, int kb) {
        #pragma unroll
        for (int ks = 0; ks < 4; ks++) {
            const int k0 = ks * 8;
            uint32_t af[2][4];
            #pragma unroll
            for (int m = 0; m < 2; m++) {
                const int rb = cx.wm * 32 + m * 16 + cx.g;
                const float* p0 = Ab + rb * APAD + k0 + cx.t;
                const float* p1 = Ab + (rb + 8) * APAD + k0 + cx.t;
                af[m][0] = f2tf32(p0[0]);
                af[m][1] = f2tf32(p1[0]);
                af[m][2] = f2tf32(p0[4]);
                af[m][3] = f2tf32(p1[4]);
            }
            #pragma unroll
            for (int n = 0; n < 8; n++) {
                const int nidx = cx.wn * 64 + n * 8 + cx.g;
                const uint32_t b0 = Bs[(kb + k0 + cx.t) * BPAD + nidx];
                const uint32_t b1 = Bs[(kb + k0 + cx.t + 4) * BPAD + nidx];
                #pragma unroll
                for (int m = 0; m < 2; m++)
                    mma_tf32(acc[m][n][0], acc[m][n][1], acc[m][n][2], acc[m][n][3],
                             af[m][0], af[m][1], af[m][2], af[m][3], b0, b1);
            }
        }
    };

    cp_wait1();
    __syncthreads();

    compute_chunk(Abuf[0], 0);
    half_sync(cx.half);
    copyA(2, a_s[0]); cp_commit();

    cp_wait1(); half_sync(cx.half);
    compute_chunk(Abuf[1], 32);
    half_sync(cx.half);
    copyA(3, a_s[1]); cp_commit();

    cp_wait1(); half_sync(cx.half);
    compute_chunk(Abuf[0], 64);

    cp_wait0(); half_sync(cx.half);
    compute_chunk(Abuf[1], 96);
}

// ===========================================================================
// Single fused kernel.
// ===========================================================================
__global__ __launch_bounds__(256, 2)
void fused_all(const float* __restrict__ nf,
               const float* __restrict__ Wk,
               const float* __restrict__ Wb,
               const float* __restrict__ ef,
               const float* __restrict__ We,
               const float* __restrict__ Web,
               const int*   __restrict__ snd,
               const int*   __restrict__ rcv,
               float* __restrict__ qkv,
               float* __restrict__ out)
{
    extern __shared__ char smem[];
    const int tid    = threadIdx.x;
    const int tileId = blockIdx.x;
    GemmCtx cx = make_ctx();
    const uint64_t pol_stream = policy_evict_first();

    if (tileId < NODE_TILES) {
        // ---------------- NODE TILE ----------------
        const int row0  = (tileId >> 2) * 128;
        const int colW0 = (tileId & 3) * 128;

        float acc[2][8][4];
        gemm_body(nf, N_NODES, 512, Wk, colW0, row0, smem, cx, acc, pol_stream);

        float2 bvs[8];
        #pragma unroll
        for (int n = 0; n < 8; n++)
            bvs[n] = *(const float2*)&Wb[colW0 + cx.wn * 64 + n * 8 + 2 * cx.t];

        float* C;
        int Cstride, colC0;
        if (colW0 == 0) { C = out; Cstride = 128; colC0 = 0; }
        else            { C = qkv; Cstride = 384; colC0 = colW0 - 128; }

        #pragma unroll
        for (int m = 0; m < 2; m++) {
            const int r0 = row0 + cx.wm * 32 + m * 16 + cx.g;
            const int r1 = r0 + 8;
            #pragma unroll
            for (int n = 0; n < 8; n++) {
                const int cc = colC0 + cx.wn * 64 + n * 8 + 2 * cx.t;
                if (r0 < N_NODES)
                    *(float2*)&C[(size_t)r0 * Cstride + cc] =
                        make_float2(acc[m][n][0] + bvs[n].x, acc[m][n][1] + bvs[n].y);
                if (r1 < N_NODES)
                    *(float2*)&C[(size_t)r1 * Cstride + cc] =
                        make_float2(acc[m][n][2] + bvs[n].x, acc[m][n][3] + bvs[n].y);
            }
        }

        // release: publish writes, then count this tile done
        __syncthreads();
        if (tid == 0) {
            __threadfence();
            atomicAdd(&g_node_done, 1u);
        }
        return;
    }

    // ---------------- EDGE TILE ----------------
    float* ep_s  = (float*)smem;                  // reuses B region post-MMA
    int*   s_snd = (int*)(smem + GEMM_SMEM);
    int*   s_rcv = (int*)(smem + GEMM_SMEM + 128 * 4);
    const uint64_t pol_keep = policy_evict_last();

    const int row0 = (tileId - NODE_TILES) * 128;

    if (tid < 128) {
        const int e = row0 + tid;
        s_snd[tid] = (e < N_EDGES) ? __ldg(&snd[e]) : 0;
    } else {
        const int e = row0 + tid - 128;
        s_rcv[tid - 128] = (e < N_EDGES) ? __ldg(&rcv[e]) : 0;
    }

    float acc[2][8][4];
    gemm_body(ef, N_EDGES, 128, We, 0, row0, smem, cx, acc, pol_stream);

    // ---- park ep (+bias) into SMEM ----
    __syncthreads();
    float2 bvs[8];
    #pragma unroll
    for (int n = 0; n < 8; n++)
        bvs[n] = *(const float2*)&Web[cx.wn * 64 + n * 8 + 2 * cx.t];

    #pragma unroll
    for (int m = 0; m < 2; m++) {
        const int r0l = cx.wm * 32 + m * 16 + cx.g;
        #pragma unroll
        for (int n = 0; n < 8; n++) {
            const int cc = cx.wn * 64 + n * 8 + 2 * cx.t;
            *(float2*)&ep_s[r0l * BPAD + cc] =
                make_float2(acc[m][n][0] + bvs[n].x, acc[m][n][1] + bvs[n].y);
            *(float2*)&ep_s[(r0l + 8) * BPAD + cc] =
                make_float2(acc[m][n][2] + bvs[n].x, acc[m][n][3] + bvs[n].y);
        }
    }

    // ---- gate: wait for all node tiles (acquire) ----
    if (tid == 0) {
        unsigned v;
        do {
            asm volatile("ld.acquire.gpu.global.u32 %0, [%1];"
                         : "=r"(v) : "l"(&g_node_done));
            if (v < NODE_TILES)
                asm volatile("nanosleep.u32 64;");
        } while (v < NODE_TILES);
    }
    __syncthreads();   // also covers the ep_s park visibility

    // ---- phase C: 4-edge ILP batches, warp-coherent ld.v4/red.v4 ----
    const int d = cx.lane * 4;
    #pragma unroll
    for (int b = 0; b < 4; b++) {
        int el[4], ss[4], rr[4];
        bool ok[4];
        #pragma unroll
        for (int i = 0; i < 4; i++) {
            el[i] = cx.wid * 16 + b * 4 + i;
            ok[i] = (row0 + el[i]) < N_EDGES;
            ss[i] = s_snd[el[i]];
            rr[i] = s_rcv[el[i]];
        }
        float4 q[4], kk[4], vv[4], epv[4];
        #pragma unroll
        for (int i = 0; i < 4; i++) {
            q[i]   = ld_keep_f4(&qkv[(size_t)rr[i] * 384 + d], pol_keep);
            kk[i]  = ld_keep_f4(&qkv[(size_t)ss[i] * 384 + 128 + d], pol_keep);
            vv[i]  = ld_keep_f4(&qkv[(size_t)ss[i] * 384 + 256 + d], pol_keep);
            epv[i] = *(const float4*)&ep_s[el[i] * BPAD + d];
        }
        #pragma unroll
        for (int i = 0; i < 4; i++) {
            float4 m;
            m.x = sigmoidf_(q[i].x + kk[i].x + epv[i].x) * vv[i].x;
            m.y = sigmoidf_(q[i].y + kk[i].y + epv[i].y) * vv[i].y;
            m.z = sigmoidf_(q[i].z + kk[i].z + epv[i].z) * vv[i].z;
            m.w = sigmoidf_(q[i].w + kk[i].w + epv[i].w) * vv[i].w;
            if (ok[i])
                red_v4(&out[(size_t)rr[i] * 128 + d], m);
        }
    }

    // ---- counter maintenance: last edge tile resets both for next replay ----
    __syncthreads();
    if (tid == 0) {
        const unsigned v = atomicAdd(&g_edge_done, 1u);
        if (v == EDGE_TILES - 1) {
            atomicExch(&g_edge_done, 0u);
            atomicExch(&g_node_done, 0u);
        }
    }
}

// ---------------------------------------------------------------------------
// Launch
// Inputs: 0 nf[50000,128] 1 snd[600000] 2 rcv[600000] 3 ef[600000,128]
//         4 Wk[128,512] 5 Wb[512] 6 Wek[128,128] 7 Web[128]
// ---------------------------------------------------------------------------
extern "C" void kernel_launch(void* const* d_in, const int* in_sizes, int n_in,
                              void* d_out, int out_size)
{
    const float* nf   = (const float*)d_in[0];
    const int*   snd  = (const int*)  d_in[1];
    const int*   rcv  = (const int*)  d_in[2];
    const float* ef   = (const float*)d_in[3];
    const float* Wk   = (const float*)d_in[4];
    const float* Wb   = (const float*)d_in[5];
    const float* Wek  = (const float*)d_in[6];
    const float* Web  = (const float*)d_in[7];
    float* out = (float*)d_out;

    float* qkv_ptr;
    cudaGetSymbolAddress((void**)&qkv_ptr, g_qkv);

    cudaFuncSetAttribute(fused_all,
                         cudaFuncAttributeMaxDynamicSharedMemorySize, FUSED_SMEM);

    fused_all<<<ALL_TILES, 256, FUSED_SMEM>>>(nf, Wk, Wb, ef, Wek, Web,
                                              snd, rcv, qkv_ptr, out);
}

// round 17
// speedup vs baseline: 1.3037x; 1.0153x over previous
#include <cuda_runtime.h>
#include <cuda_bf16.h>
#include <cstdint>

// ---------------------------------------------------------------------------
// ResidualGatedGCN — SINGLE fused kernel (R16 base).
// R17: (1) mma asm non-volatile -> compiler can pipeline LDS over MMAs;
//      (2) A fragments feed raw fp32 bits to HMMA.TF32 (drop per-fragment
//          cvt.rna; B keeps RN conversion at staging).
// ---------------------------------------------------------------------------

#define N_NODES 50000
#define N_EDGES 600000
#define NODE_TILES 1564                    // 391 row-tiles x 4 col-tiles
#define EDGE_TILES 4688                    // ceil(600000/128)
#define ALL_TILES  (NODE_TILES + EDGE_TILES)

__device__ float g_qkv[(size_t)N_NODES * 384];      // 76.8 MB
__device__ unsigned g_node_done = 0;
__device__ unsigned g_edge_done = 0;

#define KC      32
#define APAD    36
#define BPAD    136
#define A_CHUNK_BYTES (128 * APAD * 4)   // 18432
#define B_BYTES       (128 * BPAD * 4)   // 69632
#define GEMM_SMEM     (B_BYTES + 2 * A_CHUNK_BYTES)        // 106496
#define FUSED_SMEM    (GEMM_SMEM + 2 * 128 * 4)

__device__ __forceinline__ uint32_t f2tf32(float f) {
    uint32_t u;
    asm("cvt.rna.tf32.f32 %0, %1;" : "=r"(u) : "f"(f));
    return u;
}
// NON-volatile: register-only in/out, lets ptxas/compiler software-pipeline
// the next k-step's shared loads above these MMAs.
__device__ __forceinline__ void mma_tf32(float& d0, float& d1, float& d2, float& d3,
                                         uint32_t a0, uint32_t a1, uint32_t a2, uint32_t a3,
                                         uint32_t b0, uint32_t b1)
{
    asm("mma.sync.aligned.m16n8k8.row.col.f32.tf32.tf32.f32 "
        "{%0,%1,%2,%3}, {%4,%5,%6,%7}, {%8,%9}, {%0,%1,%2,%3};"
        : "+f"(d0), "+f"(d1), "+f"(d2), "+f"(d3)
        : "r"(a0), "r"(a1), "r"(a2), "r"(a3), "r"(b0), "r"(b1));
}
__device__ __forceinline__ uint32_t smem_u32(const void* p) {
    uint32_t a;
    asm("{ .reg .u64 t; cvta.to.shared.u64 t, %1; cvt.u32.u64 %0, t; }"
        : "=r"(a) : "l"(p));
    return a;
}
__device__ __forceinline__ uint64_t policy_evict_first() {
    uint64_t pol;
    asm("createpolicy.fractional.L2::evict_first.b64 %0, 1.0;" : "=l"(pol));
    return pol;
}
__device__ __forceinline__ uint64_t policy_evict_last() {
    uint64_t pol;
    asm("createpolicy.fractional.L2::evict_last.b64 %0, 1.0;" : "=l"(pol));
    return pol;
}
__device__ __forceinline__ void cp_async16_pol(uint32_t sdst, const void* gsrc,
                                               int bytes, uint64_t pol) {
    asm volatile("cp.async.cg.shared.global.L2::cache_hint [%0], [%1], 16, %2, %3;"
                 :: "r"(sdst), "l"(gsrc), "r"(bytes), "l"(pol));
}
__device__ __forceinline__ void cp_commit() {
    asm volatile("cp.async.commit_group;" ::: "memory");
}
__device__ __forceinline__ void cp_wait1() {
    asm volatile("cp.async.wait_group 1;" ::: "memory");
}
__device__ __forceinline__ void cp_wait0() {
    asm volatile("cp.async.wait_group 0;" ::: "memory");
}
__device__ __forceinline__ void half_sync(int half) {
    asm volatile("bar.sync %0, 128;" :: "r"(half + 1) : "memory");
}
__device__ __forceinline__ float4 ld_keep_f4(const float* p, uint64_t pol) {
    float4 v;
    asm volatile("ld.global.nc.L2::cache_hint.v4.f32 {%0,%1,%2,%3}, [%4], %5;"
                 : "=f"(v.x), "=f"(v.y), "=f"(v.z), "=f"(v.w)
                 : "l"(p), "l"(pol));
    return v;
}
__device__ __forceinline__ float sigmoidf_(float x) {
    return 1.0f / (1.0f + __expf(-x));
}
__device__ __forceinline__ void red_v4(float* p, float4 m) {
    asm volatile("red.global.add.v4.f32 [%0], {%1,%2,%3,%4};"
                 :: "l"(p), "f"(m.x), "f"(m.y), "f"(m.z), "f"(m.w));
}

struct GemmCtx { int wid, lane, g, t, wm, wn, half, htid; };

__device__ __forceinline__ GemmCtx make_ctx() {
    GemmCtx cx;
    const int tid = threadIdx.x;
    cx.wid = tid >> 5; cx.lane = tid & 31;
    cx.g = cx.lane >> 2; cx.t = cx.lane & 3;
    cx.wm = cx.wid >> 1; cx.wn = cx.wid & 1;
    cx.half = tid >> 7;
    cx.htid = tid & 127;
    return cx;
}

// ===========================================================================
// Split-half 128x128 K=128 tf32 GEMM body.
// A fragments: raw fp32 bits (HMMA.TF32 uses upper 19 bits; truncation).
// B: RN-converted once at staging.
// ===========================================================================
__device__ __forceinline__
void gemm_body(const float* __restrict__ A, int M, int Wstride,
               const float* __restrict__ W, int colW0,
               int row0, char* smem, const GemmCtx& cx,
               float acc[2][8][4], uint64_t pol)
{
    uint32_t* Bs = (uint32_t*)smem;
    const uint32_t* Abuf[2] = { (const uint32_t*)(smem + B_BYTES),
                                (const uint32_t*)(smem + B_BYTES + A_CHUNK_BYTES) };
    const uint32_t sbase = smem_u32(smem);
    const uint32_t a_s[2] = { sbase + B_BYTES, sbase + B_BYTES + A_CHUNK_BYTES };
    const int tid = threadIdx.x;

    auto copyA = [&](int chunk, uint32_t sdst) {
        #pragma unroll
        for (int j = 0; j < 4; j++) {
            const int idx = cx.htid + j * 128;
            const int r   = cx.half * 64 + (idx >> 3);
            const int seg = idx & 7;
            const int gr  = row0 + r;
            const int bytes = (gr < M) ? 16 : 0;
            const int grc = (gr < M) ? gr : (M - 1);
            cp_async16_pol(sdst + (r * APAD + seg * 4) * 4,
                           A + (size_t)grc * 128 + chunk * KC + seg * 4, bytes, pol);
        }
    };

    copyA(0, a_s[0]); cp_commit();

    #pragma unroll
    for (int it = 0; it < 16; it++) {
        const int idx = tid + it * 256;
        const int k   = idx >> 5;
        const int n4  = (idx & 31) * 4;
        const float4 v = *(const float4*)&W[(size_t)k * Wstride + colW0 + n4];
        uint4 o;
        o.x = f2tf32(v.x); o.y = f2tf32(v.y); o.z = f2tf32(v.z); o.w = f2tf32(v.w);
        *(uint4*)&Bs[k * BPAD + n4] = o;
    }

    copyA(1, a_s[1]); cp_commit();

    #pragma unroll
    for (int m = 0; m < 2; m++)
        #pragma unroll
        for (int n = 0; n < 8; n++)
            #pragma unroll
            for (int j = 0; j < 4; j++) acc[m][n][j] = 0.f;

    auto compute_chunk = [&](const uint32_t* __restrict__ Ab, int kb) {
        #pragma unroll
        for (int ks = 0; ks < 4; ks++) {
            const int k0 = ks * 8;
            uint32_t af[2][4];
            #pragma unroll
            for (int m = 0; m < 2; m++) {
                const int rb = cx.wm * 32 + m * 16 + cx.g;
                const uint32_t* p0 = Ab + rb * APAD + k0 + cx.t;
                const uint32_t* p1 = Ab + (rb + 8) * APAD + k0 + cx.t;
                af[m][0] = p0[0];
                af[m][1] = p1[0];
                af[m][2] = p0[4];
                af[m][3] = p1[4];
            }
            #pragma unroll
            for (int n = 0; n < 8; n++) {
                const int nidx = cx.wn * 64 + n * 8 + cx.g;
                const uint32_t b0 = Bs[(kb + k0 + cx.t) * BPAD + nidx];
                const uint32_t b1 = Bs[(kb + k0 + cx.t + 4) * BPAD + nidx];
                #pragma unroll
                for (int m = 0; m < 2; m++)
                    mma_tf32(acc[m][n][0], acc[m][n][1], acc[m][n][2], acc[m][n][3],
                             af[m][0], af[m][1], af[m][2], af[m][3], b0, b1);
            }
        }
    };

    cp_wait1();
    __syncthreads();

    compute_chunk(Abuf[0], 0);
    half_sync(cx.half);
    copyA(2, a_s[0]); cp_commit();

    cp_wait1(); half_sync(cx.half);
    compute_chunk(Abuf[1], 32);
    half_sync(cx.half);
    copyA(3, a_s[1]); cp_commit();

    cp_wait1(); half_sync(cx.half);
    compute_chunk(Abuf[0], 64);

    cp_wait0(); half_sync(cx.half);
    compute_chunk(Abuf[1], 96);
}

// ===========================================================================
// Single fused kernel.
// ===========================================================================
__global__ __launch_bounds__(256, 2)
void fused_all(const float* __restrict__ nf,
               const float* __restrict__ Wk,
               const float* __restrict__ Wb,
               const float* __restrict__ ef,
               const float* __restrict__ We,
               const float* __restrict__ Web,
               const int*   __restrict__ snd,
               const int*   __restrict__ rcv,
               float* __restrict__ qkv,
               float* __restrict__ out)
{
    extern __shared__ char smem[];
    const int tid    = threadIdx.x;
    const int tileId = blockIdx.x;
    GemmCtx cx = make_ctx();
    const uint64_t pol_stream = policy_evict_first();

    if (tileId < NODE_TILES) {
        // ---------------- NODE TILE ----------------
        const int row0  = (tileId >> 2) * 128;
        const int colW0 = (tileId & 3) * 128;

        float acc[2][8][4];
        gemm_body(nf, N_NODES, 512, Wk, colW0, row0, smem, cx, acc, pol_stream);

        float2 bvs[8];
        #pragma unroll
        for (int n = 0; n < 8; n++)
            bvs[n] = *(const float2*)&Wb[colW0 + cx.wn * 64 + n * 8 + 2 * cx.t];

        float* C;
        int Cstride, colC0;
        if (colW0 == 0) { C = out; Cstride = 128; colC0 = 0; }
        else            { C = qkv; Cstride = 384; colC0 = colW0 - 128; }

        #pragma unroll
        for (int m = 0; m < 2; m++) {
            const int r0 = row0 + cx.wm * 32 + m * 16 + cx.g;
            const int r1 = r0 + 8;
            #pragma unroll
            for (int n = 0; n < 8; n++) {
                const int cc = colC0 + cx.wn * 64 + n * 8 + 2 * cx.t;
                if (r0 < N_NODES)
                    *(float2*)&C[(size_t)r0 * Cstride + cc] =
                        make_float2(acc[m][n][0] + bvs[n].x, acc[m][n][1] + bvs[n].y);
                if (r1 < N_NODES)
                    *(float2*)&C[(size_t)r1 * Cstride + cc] =
                        make_float2(acc[m][n][2] + bvs[n].x, acc[m][n][3] + bvs[n].y);
            }
        }

        __syncthreads();
        if (tid == 0) {
            __threadfence();
            atomicAdd(&g_node_done, 1u);
        }
        return;
    }

    // ---------------- EDGE TILE ----------------
    float* ep_s  = (float*)smem;                  // reuses B region post-MMA
    int*   s_snd = (int*)(smem + GEMM_SMEM);
    int*   s_rcv = (int*)(smem + GEMM_SMEM + 128 * 4);
    const uint64_t pol_keep = policy_evict_last();

    const int row0 = (tileId - NODE_TILES) * 128;

    if (tid < 128) {
        const int e = row0 + tid;
        s_snd[tid] = (e < N_EDGES) ? __ldg(&snd[e]) : 0;
    } else {
        const int e = row0 + tid - 128;
        s_rcv[tid - 128] = (e < N_EDGES) ? __ldg(&rcv[e]) : 0;
    }

    float acc[2][8][4];
    gemm_body(ef, N_EDGES, 128, We, 0, row0, smem, cx, acc, pol_stream);

    // ---- park ep (+bias) into SMEM ----
    __syncthreads();
    float2 bvs[8];
    #pragma unroll
    for (int n = 0; n < 8; n++)
        bvs[n] = *(const float2*)&Web[cx.wn * 64 + n * 8 + 2 * cx.t];

    #pragma unroll
    for (int m = 0; m < 2; m++) {
        const int r0l = cx.wm * 32 + m * 16 + cx.g;
        #pragma unroll
        for (int n = 0; n < 8; n++) {
            const int cc = cx.wn * 64 + n * 8 + 2 * cx.t;
            *(float2*)&ep_s[r0l * BPAD + cc] =
                make_float2(acc[m][n][0] + bvs[n].x, acc[m][n][1] + bvs[n].y);
            *(float2*)&ep_s[(r0l + 8) * BPAD + cc] =
                make_float2(acc[m][n][2] + bvs[n].x, acc[m][n][3] + bvs[n].y);
        }
    }

    // ---- gate: wait for all node tiles (acquire) ----
    if (tid == 0) {
        unsigned v;
        do {
            asm volatile("ld.acquire.gpu.global.u32 %0, [%1];"
                         : "=r"(v) : "l"(&g_node_done));
            if (v < NODE_TILES)
                asm volatile("nanosleep.u32 64;");
        } while (v < NODE_TILES);
    }
    __syncthreads();   // also covers ep_s park visibility

    // ---- phase C: 4-edge ILP batches, warp-coherent ld.v4/red.v4 ----
    const int d = cx.lane * 4;
    #pragma unroll
    for (int b = 0; b < 4; b++) {
        int el[4], ss[4], rr[4];
        bool ok[4];
        #pragma unroll
        for (int i = 0; i < 4; i++) {
            el[i] = cx.wid * 16 + b * 4 + i;
            ok[i] = (row0 + el[i]) < N_EDGES;
            ss[i] = s_snd[el[i]];
            rr[i] = s_rcv[el[i]];
        }
        float4 q[4], kk[4], vv[4], epv[4];
        #pragma unroll
        for (int i = 0; i < 4; i++) {
            q[i]   = ld_keep_f4(&qkv[(size_t)rr[i] * 384 + d], pol_keep);
            kk[i]  = ld_keep_f4(&qkv[(size_t)ss[i] * 384 + 128 + d], pol_keep);
            vv[i]  = ld_keep_f4(&qkv[(size_t)ss[i] * 384 + 256 + d], pol_keep);
            epv[i] = *(const float4*)&ep_s[el[i] * BPAD + d];
        }
        #pragma unroll
        for (int i = 0; i < 4; i++) {
            float4 m;
            m.x = sigmoidf_(q[i].x + kk[i].x + epv[i].x) * vv[i].x;
            m.y = sigmoidf_(q[i].y + kk[i].y + epv[i].y) * vv[i].y;
            m.z = sigmoidf_(q[i].z + kk[i].z + epv[i].z) * vv[i].z;
            m.w = sigmoidf_(q[i].w + kk[i].w + epv[i].w) * vv[i].w;
            if (ok[i])
                red_v4(&out[(size_t)rr[i] * 128 + d], m);
        }
    }

    // ---- counter maintenance: last edge tile resets both for next replay ----
    __syncthreads();
    if (tid == 0) {
        const unsigned v = atomicAdd(&g_edge_done, 1u);
        if (v == EDGE_TILES - 1) {
            atomicExch(&g_edge_done, 0u);
            atomicExch(&g_node_done, 0u);
        }
    }
}

// ---------------------------------------------------------------------------
// Launch
// Inputs: 0 nf[50000,128] 1 snd[600000] 2 rcv[600000] 3 ef[600000,128]
//         4 Wk[128,512] 5 Wb[512] 6 Wek[128,128] 7 Web[128]
// ---------------------------------------------------------------------------
extern "C" void kernel_launch(void* const* d_in, const int* in_sizes, int n_in,
                              void* d_out, int out_size)
{
    const float* nf   = (const float*)d_in[0];
    const int*   snd  = (const int*)  d_in[1];
    const int*   rcv  = (const int*)  d_in[2];
    const float* ef   = (const float*)d_in[3];
    const float* Wk   = (const float*)d_in[4];
    const float* Wb   = (const float*)d_in[5];
    const float* Wek  = (const float*)d_in[6];
    const float* Web  = (const float*)d_in[7];
    float* out = (float*)d_out;

    float* qkv_ptr;
    cudaGetSymbolAddress((void**)&qkv_ptr, g_qkv);

    cudaFuncSetAttribute(fused_all,
                         cudaFuncAttributeMaxDynamicSharedMemorySize, FUSED_SMEM);

    fused_all<<<ALL_TILES, 256, FUSED_SMEM>>>(nf, Wk, Wb, ef, Wek, Web,
                                              snd, rcv, qkv_ptr, out);
}